// round 1
// baseline (speedup 1.0000x reference)
#include <cuda_runtime.h>
#include <cuda_bf16.h>
#include <math_constants.h>

// Problem constants (from reference setup_inputs)
#define NU   8192     // unlabeled rows (anchor / positive)
#define NL   8192     // labeled rows PER HALF (16384 / 2)
#define DD   512      // feature dim
#define CC   1000     // num classes
#define INV_TAU 10.0f

// ---------------- device scratch (static globals; no allocation) -------------
__device__ float g_aq [NU * DD];          // normalized anchor
__device__ float g_pq [NU * DD];          // normalized positive
__device__ float g_sup[2 * NL * DD];      // normalized lb_feat (both halves)
__device__ float g_logits[(size_t)NU * NL]; // 268 MB, reused per half
__device__ int   g_labels[2 * NL];
__device__ int   g_counts[2 * CC];
__device__ int   g_offsets[2 * (CC + 1)];
__device__ int   g_cursor[2 * CC];
__device__ int   g_perm[2 * NL];

// ---------------- simple vectorized copy ------------------------------------
__global__ void copy_f4(const float4* __restrict__ src, float4* __restrict__ dst, int n4) {
    int i = blockIdx.x * blockDim.x + threadIdx.x;
    if (i < n4) dst[i] = src[i];
}

// ---------------- labels from one-hot (warp per row) -------------------------
__global__ void labels_k(const float* __restrict__ oh) {
    int row  = blockIdx.x * (blockDim.x >> 5) + (threadIdx.x >> 5);
    int lane = threadIdx.x & 31;
    if (row >= 2 * NL) return;
    const float* r = oh + (size_t)row * CC;
    int lab = -1;
    for (int c = lane; c < CC; c += 32)
        if (r[c] > 0.5f) lab = c;
    #pragma unroll
    for (int o = 16; o; o >>= 1) lab = max(lab, __shfl_xor_sync(0xffffffffu, lab, o));
    if (lane == 0) g_labels[row] = lab;
}

__global__ void zero_counts_k() {
    int i = blockIdx.x * blockDim.x + threadIdx.x;
    if (i < 2 * CC) g_counts[i] = 0;
}

__global__ void count_k() {
    int i = blockIdx.x * blockDim.x + threadIdx.x;
    if (i >= 2 * NL) return;
    int half = i / NL;
    atomicAdd(&g_counts[half * CC + g_labels[i]], 1);
}

// serial prefix per half (trivial work)
__global__ void offsets_k() {
    int h = threadIdx.x;
    if (h >= 2) return;
    int off = 0;
    for (int c = 0; c < CC; c++) {
        g_offsets[h * (CC + 1) + c] = off;
        g_cursor[h * CC + c] = off;
        off += g_counts[h * CC + c];
    }
    g_offsets[h * (CC + 1) + CC] = off;
}

__global__ void scatter_k() {
    int i = blockIdx.x * blockDim.x + threadIdx.x;
    if (i >= 2 * NL) return;
    int half = i / NL;
    int s    = i - half * NL;
    int pos  = atomicAdd(&g_cursor[half * CC + g_labels[i]], 1);
    g_perm[half * NL + pos] = s;
}

// ---------------- l2 normalize (warp per row) --------------------------------
// sel: 0 -> g_aq, 1 -> g_pq, 2 -> g_sup
__global__ void norm_k(const float* __restrict__ src, int sel, int rows) {
    int row  = blockIdx.x * (blockDim.x >> 5) + (threadIdx.x >> 5);
    int lane = threadIdx.x & 31;
    if (row >= rows) return;
    float* dstbase = (sel == 0) ? g_aq : (sel == 1) ? g_pq : g_sup;
    const float* s = src + (size_t)row * DD;
    float v[16];
    float acc = 0.f;
    #pragma unroll
    for (int i = 0; i < 16; i++) { v[i] = s[lane + 32 * i]; acc += v[i] * v[i]; }
    #pragma unroll
    for (int o = 16; o; o >>= 1) acc += __shfl_xor_sync(0xffffffffu, acc, o);
    float inv = 1.0f / fmaxf(sqrtf(acc), 1e-12f);
    float* d = dstbase + (size_t)row * DD;
    #pragma unroll
    for (int i = 0; i < 16; i++) d[lane + 32 * i] = v[i] * inv;
}

// ---------------- fp32 SGEMM: logits = (Q @ K^T) / TAU -----------------------
// Q: [NU, DD] row-major, K: [NL, DD] row-major. 128x128 tile, 8x8 per thread.
#define BM 128
#define BN 128
#define BK 16
__global__ void __launch_bounds__(256) gemm_k(int qsel) {
    __shared__ float As[BK][BM];
    __shared__ float Bs[BK][BN];

    const float* Q  = (qsel == 0) ? g_aq : g_pq;
    const float* Kt = g_sup + (size_t)qsel * NL * DD;

    int bx = blockIdx.x;   // N tile
    int by = blockIdx.y;   // M tile
    int tid = threadIdx.x;
    int tx = tid & 15;     // 0..15
    int ty = tid >> 4;     // 0..15

    const float* Aptr = Q  + (size_t)by * BM * DD;
    const float* Bptr = Kt + (size_t)bx * BN * DD;

    float acc[8][8];
    #pragma unroll
    for (int i = 0; i < 8; i++)
        #pragma unroll
        for (int j = 0; j < 8; j++) acc[i][j] = 0.f;

    for (int k0 = 0; k0 < DD; k0 += BK) {
        #pragma unroll
        for (int r = 0; r < 2; r++) {
            int f   = tid + r * 256;   // 0..511 float4 slots
            int row = f >> 2;
            int c4  = (f & 3) * 4;
            float4 va = *(const float4*)(Aptr + row * DD + k0 + c4);
            As[c4 + 0][row] = va.x; As[c4 + 1][row] = va.y;
            As[c4 + 2][row] = va.z; As[c4 + 3][row] = va.w;
            float4 vb = *(const float4*)(Bptr + row * DD + k0 + c4);
            Bs[c4 + 0][row] = vb.x; Bs[c4 + 1][row] = vb.y;
            Bs[c4 + 2][row] = vb.z; Bs[c4 + 3][row] = vb.w;
        }
        __syncthreads();
        #pragma unroll
        for (int kk = 0; kk < BK; kk++) {
            float a[8], b[8];
            #pragma unroll
            for (int i = 0; i < 8; i++) a[i] = As[kk][ty * 8 + i];
            #pragma unroll
            for (int j = 0; j < 8; j++) b[j] = Bs[kk][tx * 8 + j];
            #pragma unroll
            for (int i = 0; i < 8; i++)
                #pragma unroll
                for (int j = 0; j < 8; j++) acc[i][j] += a[i] * b[j];
        }
        __syncthreads();
    }

    #pragma unroll
    for (int i = 0; i < 8; i++) {
        int m = by * BM + ty * 8 + i;
        float* orow = g_logits + (size_t)m * NL + bx * BN + tx * 8;
        #pragma unroll
        for (int j = 0; j < 8; j++) orow[j] = acc[i][j] * INV_TAU;
    }
}

// ---------------- fused softmax + class aggregation --------------------------
// One CTA (256 thr) per anchor row. Row of logits in smem, block-reduce
// max & sum, then per-class gathered sums via sorted perm list.
__global__ void __launch_bounds__(256) softmax_agg_k(int half, float* __restrict__ out) {
    __shared__ float sv[NL];      // 32 KB
    __shared__ float red[256];

    int u = blockIdx.x;
    int tid = threadIdx.x;
    const float* lrow = g_logits + (size_t)u * NL;
    const int* perm = g_perm + half * NL;
    const int* offs = g_offsets + half * (CC + 1);

    float lmax = -CUDART_INF_F;
    for (int i = tid; i < NL; i += 256) {
        float v = lrow[i];
        sv[i] = v;
        lmax = fmaxf(lmax, v);
    }
    red[tid] = lmax;
    __syncthreads();
    #pragma unroll
    for (int s = 128; s > 0; s >>= 1) {
        if (tid < s) red[tid] = fmaxf(red[tid], red[tid + s]);
        __syncthreads();
    }
    float m = red[0];
    __syncthreads();

    float lsum = 0.f;
    for (int i = tid; i < NL; i += 256) {
        float e = __expf(sv[i] - m);
        sv[i] = e;
        lsum += e;
    }
    red[tid] = lsum;
    __syncthreads();
    #pragma unroll
    for (int s = 128; s > 0; s >>= 1) {
        if (tid < s) red[tid] += red[tid + s];
        __syncthreads();
    }
    float inv = 1.0f / red[0];
    __syncthreads();

    float* orow = out + (size_t)u * CC;
    for (int c = tid; c < CC; c += 256) {
        int b = offs[c], e = offs[c + 1];
        float s = 0.f;
        for (int j = b; j < e; j++) s += sv[perm[j]];
        orow[c] = s * inv;
    }
}

// ---------------- launch ------------------------------------------------------
extern "C" void kernel_launch(void* const* d_in, const int* in_sizes, int n_in,
                              void* d_out, int out_size) {
    const float* anchor = (const float*)d_in[0];
    const float* pos    = (const float*)d_in[1];
    const float* lb     = (const float*)d_in[2];
    const float* oh     = (const float*)d_in[3];
    const float* lgx    = (const float*)d_in[4];
    float* out = (float*)d_out;

    // Output layout (concatenated tuple, element offsets)
    const size_t nA  = (size_t)NU * DD;        // anchor_feat
    const size_t nP  = (size_t)NU * DD;        // positive_feat
    const size_t nL  = (size_t)2 * NL * DD;    // lb_feat
    const size_t nOH = (size_t)2 * NL * CC;    // lb_one_hot
    const size_t nLG = (size_t)2 * NL * CC;    // logits_x_lb
    size_t oA  = 0;
    size_t oP  = oA + nA;
    size_t oL  = oP + nP;
    size_t oOH = oL + nL;
    size_t oLG = oOH + nOH;
    size_t oU1 = oLG + nLG;
    size_t oU2 = oU1 + (size_t)NU * CC;

    // 1) pass-through copies
    copy_f4<<<(int)(nA  / 4 + 255) / 256, 256>>>((const float4*)anchor, (float4*)(out + oA),  (int)(nA  / 4));
    copy_f4<<<(int)(nP  / 4 + 255) / 256, 256>>>((const float4*)pos,    (float4*)(out + oP),  (int)(nP  / 4));
    copy_f4<<<(int)(nL  / 4 + 255) / 256, 256>>>((const float4*)lb,     (float4*)(out + oL),  (int)(nL  / 4));
    copy_f4<<<(int)(nOH / 4 + 255) / 256, 256>>>((const float4*)oh,     (float4*)(out + oOH), (int)(nOH / 4));
    copy_f4<<<(int)(nLG / 4 + 255) / 256, 256>>>((const float4*)lgx,    (float4*)(out + oLG), (int)(nLG / 4));

    // 2) labels + counting sort (per half)
    labels_k<<<(2 * NL) / 8, 256>>>(oh);
    zero_counts_k<<<(2 * CC + 255) / 256, 256>>>();
    count_k<<<(2 * NL + 255) / 256, 256>>>();
    offsets_k<<<1, 2>>>();
    scatter_k<<<(2 * NL + 255) / 256, 256>>>();

    // 3) l2 normalize
    norm_k<<<NU / 8, 256>>>(anchor, 0, NU);
    norm_k<<<NU / 8, 256>>>(pos,    1, NU);
    norm_k<<<(2 * NL) / 8, 256>>>(lb, 2, 2 * NL);

    // 4) half 1: anchor vs supports[0:NL]
    dim3 gg(NL / BN, NU / BM);
    gemm_k<<<gg, 256>>>(0);
    softmax_agg_k<<<NU, 256>>>(0, out + oU1);

    // 5) half 2: positive vs supports[NL:2NL]
    gemm_k<<<gg, 256>>>(1);
    softmax_agg_k<<<NU, 256>>>(1, out + oU2);
}

// round 3
// speedup vs baseline: 3.9403x; 3.9403x over previous
#include <cuda_runtime.h>
#include <cuda_bf16.h>
#include <math_constants.h>
#include <cstdint>

// Problem constants
#define NU   8192
#define NL   8192     // per half
#define DD   512
#define CC   1000
#define INV_TAU 10.0f

// ---------------- device scratch ---------------------------------------------
__device__ __nv_bfloat16 g_aqh [NU * DD];
__device__ __nv_bfloat16 g_pqh [NU * DD];
__device__ __nv_bfloat16 g_suph[2 * NL * DD];
__device__ float g_logits[2 * (size_t)NU * NL];
__device__ int   g_labels[2 * NL];
__device__ int   g_counts[2 * CC];
__device__ int   g_offsets[2 * (CC + 1)];
__device__ int   g_cursor[2 * CC];
__device__ int   g_perm[2 * NL];

// ---------------- PTX helpers (sm_80-era, family-common) ----------------------
__device__ __forceinline__ uint32_t smem_u32(const void* p) {
    uint32_t a;
    asm("{ .reg .u64 t; cvta.to.shared.u64 t, %1; cvt.u32.u64 %0, t; }" : "=r"(a) : "l"(p));
    return a;
}
#define CP_ASYNC16(s, g) asm volatile("cp.async.cg.shared.global [%0], [%1], 16;" :: "r"(s), "l"(g))
#define CP_COMMIT()      asm volatile("cp.async.commit_group;" ::: "memory")
#define CP_WAIT(n)       asm volatile("cp.async.wait_group %0;" :: "n"(n) : "memory")

__device__ __forceinline__ void ldsm_x4(uint32_t* r, uint32_t addr) {
    asm volatile("ldmatrix.sync.aligned.m8n8.x4.shared.b16 {%0,%1,%2,%3}, [%4];"
        : "=r"(r[0]), "=r"(r[1]), "=r"(r[2]), "=r"(r[3]) : "r"(addr));
}
__device__ __forceinline__ void ldsm_x2(uint32_t* r, uint32_t addr) {
    asm volatile("ldmatrix.sync.aligned.m8n8.x2.shared.b16 {%0,%1}, [%2];"
        : "=r"(r[0]), "=r"(r[1]) : "r"(addr));
}
__device__ __forceinline__ void mma_bf16(float* c, const uint32_t* a, const uint32_t* b) {
    asm volatile("mma.sync.aligned.m16n8k16.row.col.f32.bf16.bf16.f32 "
        "{%0,%1,%2,%3},{%4,%5,%6,%7},{%8,%9},{%0,%1,%2,%3};"
        : "+f"(c[0]), "+f"(c[1]), "+f"(c[2]), "+f"(c[3])
        : "r"(a[0]), "r"(a[1]), "r"(a[2]), "r"(a[3]), "r"(b[0]), "r"(b[1]));
}

// ---------------- copies ------------------------------------------------------
__global__ void copy_f4(const float4* __restrict__ src, float4* __restrict__ dst, int n4) {
    int i = blockIdx.x * blockDim.x + threadIdx.x;
    if (i < n4) dst[i] = src[i];
}

// ---------------- labels + counting sort -------------------------------------
__global__ void labels_k(const float* __restrict__ oh) {
    int row  = blockIdx.x * (blockDim.x >> 5) + (threadIdx.x >> 5);
    int lane = threadIdx.x & 31;
    if (row >= 2 * NL) return;
    const float* r = oh + (size_t)row * CC;
    int lab = -1;
    for (int c = lane; c < CC; c += 32)
        if (r[c] > 0.5f) lab = c;
    #pragma unroll
    for (int o = 16; o; o >>= 1) lab = max(lab, __shfl_xor_sync(0xffffffffu, lab, o));
    if (lane == 0) g_labels[row] = lab;
}
__global__ void zero_counts_k() {
    int i = blockIdx.x * blockDim.x + threadIdx.x;
    if (i < 2 * CC) g_counts[i] = 0;
}
__global__ void count_k() {
    int i = blockIdx.x * blockDim.x + threadIdx.x;
    if (i >= 2 * NL) return;
    int half = i / NL;
    atomicAdd(&g_counts[half * CC + g_labels[i]], 1);
}
__global__ void offsets_k() {
    int h = threadIdx.x;
    if (h >= 2) return;
    int off = 0;
    for (int c = 0; c < CC; c++) {
        g_offsets[h * (CC + 1) + c] = off;
        g_cursor[h * CC + c] = off;
        off += g_counts[h * CC + c];
    }
    g_offsets[h * (CC + 1) + CC] = off;
}
__global__ void scatter_k() {
    int i = blockIdx.x * blockDim.x + threadIdx.x;
    if (i >= 2 * NL) return;
    int half = i / NL;
    int s    = i - half * NL;
    int pos  = atomicAdd(&g_cursor[half * CC + g_labels[i]], 1);
    g_perm[half * NL + pos] = s;
}

// ---------------- l2 normalize -> bf16 ---------------------------------------
__global__ void norm_k(const float* __restrict__ src, int sel, int rows) {
    int row  = blockIdx.x * (blockDim.x >> 5) + (threadIdx.x >> 5);
    int lane = threadIdx.x & 31;
    if (row >= rows) return;
    __nv_bfloat16* dstbase = (sel == 0) ? g_aqh : (sel == 1) ? g_pqh : g_suph;
    const float* s = src + (size_t)row * DD;
    float v[16];
    float acc = 0.f;
    #pragma unroll
    for (int i = 0; i < 16; i++) { v[i] = s[lane + 32 * i]; acc += v[i] * v[i]; }
    #pragma unroll
    for (int o = 16; o; o >>= 1) acc += __shfl_xor_sync(0xffffffffu, acc, o);
    float inv = 1.0f / fmaxf(sqrtf(acc), 1e-12f);
    __nv_bfloat16* d = dstbase + (size_t)row * DD;
    #pragma unroll
    for (int i = 0; i < 16; i++) d[lane + 32 * i] = __float2bfloat16(v[i] * inv);
}

// ---------------- bf16 mma.sync GEMM: logits = (Q @ K^T) * INV_TAU -----------
// 128x128 tile, BK=32, 8 warps (each 64x32), 4-stage cp.async pipeline.
#define BM 128
#define BN 128
#define BKK 32
#define STAGES 4
#define NKIT (DD / BKK)                 // 16
#define SROW 80                         // padded row bytes (32 bf16 = 64B + 16B pad)
#define TILE_BYTES (BM * SROW)          // 10240
#define STAGE_BYTES (2 * TILE_BYTES)    // 20480
#define GEMM_SMEM (STAGES * STAGE_BYTES)  // 81920

__global__ void __launch_bounds__(256) gemm_mma_k() {
    extern __shared__ __align__(16) char smem[];
    const uint32_t sbase = smem_u32(smem);

    const int tid  = threadIdx.x;
    const int wid  = tid >> 5;
    const int lane = tid & 31;
    const int wr   = wid & 1;      // warp row (0..1) -> 64 rows each
    const int wc   = wid >> 1;     // warp col (0..3) -> 32 cols each

    const int z  = blockIdx.z;
    const __nv_bfloat16* A = (z == 0) ? g_aqh : g_pqh;
    const __nv_bfloat16* B = g_suph + (size_t)z * NL * DD;
    const int m0 = blockIdx.y * BM;
    const int n0 = blockIdx.x * BN;
    const __nv_bfloat16* Abase = A + (size_t)m0 * DD;
    const __nv_bfloat16* Bbase = B + (size_t)n0 * DD;

    // load mapping: 512 16B-chunks per tile / 256 threads = 2 chunks each
    const int r0 = (tid >> 2), r1 = ((tid + 256) >> 2);
    const int c0 = (tid & 3) * 8, c1 = c0;  // chunk col (bf16 elems)

    float acc[4][4][4];
    #pragma unroll
    for (int mi = 0; mi < 4; mi++)
        #pragma unroll
        for (int ni = 0; ni < 4; ni++)
            #pragma unroll
            for (int q = 0; q < 4; q++) acc[mi][ni][q] = 0.f;

    // prefetch stages 0..STAGES-2
    #pragma unroll
    for (int s = 0; s < STAGES - 1; s++) {
        uint32_t sA = sbase + s * STAGE_BYTES;
        uint32_t sB = sA + TILE_BYTES;
        const __nv_bfloat16* Ak = Abase + s * BKK;
        const __nv_bfloat16* Bk = Bbase + s * BKK;
        CP_ASYNC16(sA + r0 * SROW + (c0 * 2), Ak + (size_t)r0 * DD + c0);
        CP_ASYNC16(sA + r1 * SROW + (c1 * 2), Ak + (size_t)r1 * DD + c1);
        CP_ASYNC16(sB + r0 * SROW + (c0 * 2), Bk + (size_t)r0 * DD + c0);
        CP_ASYNC16(sB + r1 * SROW + (c1 * 2), Bk + (size_t)r1 * DD + c1);
        CP_COMMIT();
    }

    // ldmatrix base offsets (within a stage)
    const uint32_t aOff = (uint32_t)(wr * 64 + (lane & 15)) * SROW + (lane >> 4) * 16;
    const uint32_t bOff = (uint32_t)(wc * 32 + (lane & 7)) * SROW + ((lane >> 3) & 1) * 16;

    for (int kc = 0; kc < NKIT; kc++) {
        const int st = kc % STAGES;
        const int pf = kc + STAGES - 1;
        if (pf < NKIT) {
            const int ps = pf % STAGES;
            uint32_t sA = sbase + ps * STAGE_BYTES;
            uint32_t sB = sA + TILE_BYTES;
            const __nv_bfloat16* Ak = Abase + pf * BKK;
            const __nv_bfloat16* Bk = Bbase + pf * BKK;
            CP_ASYNC16(sA + r0 * SROW + (c0 * 2), Ak + (size_t)r0 * DD + c0);
            CP_ASYNC16(sA + r1 * SROW + (c1 * 2), Ak + (size_t)r1 * DD + c1);
            CP_ASYNC16(sB + r0 * SROW + (c0 * 2), Bk + (size_t)r0 * DD + c0);
            CP_ASYNC16(sB + r1 * SROW + (c1 * 2), Bk + (size_t)r1 * DD + c1);
        }
        CP_COMMIT();
        CP_WAIT(STAGES - 1);
        __syncthreads();

        const uint32_t sA = sbase + st * STAGE_BYTES;
        const uint32_t sB = sA + TILE_BYTES;
        #pragma unroll
        for (int kk = 0; kk < 2; kk++) {
            uint32_t aF[4][4], bF[4][2];
            #pragma unroll
            for (int mi = 0; mi < 4; mi++)
                ldsm_x4(aF[mi], sA + aOff + (uint32_t)mi * 16 * SROW + kk * 32);
            #pragma unroll
            for (int ni = 0; ni < 4; ni++)
                ldsm_x2(bF[ni], sB + bOff + (uint32_t)ni * 8 * SROW + kk * 32);
            #pragma unroll
            for (int mi = 0; mi < 4; mi++)
                #pragma unroll
                for (int ni = 0; ni < 4; ni++)
                    mma_bf16(acc[mi][ni], aF[mi], bF[ni]);
        }
        __syncthreads();
    }

    // epilogue: scale by 1/tau, write fp32 logits
    float* outz = g_logits + (size_t)z * NU * NL;
    const int erow = m0 + wr * 64 + (lane >> 2);
    const int ecol = n0 + wc * 32 + (lane & 3) * 2;
    #pragma unroll
    for (int mi = 0; mi < 4; mi++) {
        #pragma unroll
        for (int ni = 0; ni < 4; ni++) {
            float2 v0 = make_float2(acc[mi][ni][0] * INV_TAU, acc[mi][ni][1] * INV_TAU);
            float2 v1 = make_float2(acc[mi][ni][2] * INV_TAU, acc[mi][ni][3] * INV_TAU);
            *(float2*)(outz + (size_t)(erow + mi * 16) * NL + ecol + ni * 8) = v0;
            *(float2*)(outz + (size_t)(erow + mi * 16 + 8) * NL + ecol + ni * 8) = v1;
        }
    }
}

// ---------------- fused softmax + class aggregation --------------------------
__global__ void __launch_bounds__(256) softmax_agg_k(int half, float* __restrict__ out) {
    __shared__ float sv[NL];
    __shared__ float red[256];

    int u = blockIdx.x;
    int tid = threadIdx.x;
    const float* lrow = g_logits + (size_t)half * NU * NL + (size_t)u * NL;
    const int* perm = g_perm + half * NL;
    const int* offs = g_offsets + half * (CC + 1);

    float lmax = -CUDART_INF_F;
    for (int i = tid; i < NL; i += 256) {
        float v = lrow[i];
        sv[i] = v;
        lmax = fmaxf(lmax, v);
    }
    red[tid] = lmax;
    __syncthreads();
    #pragma unroll
    for (int s = 128; s > 0; s >>= 1) {
        if (tid < s) red[tid] = fmaxf(red[tid], red[tid + s]);
        __syncthreads();
    }
    float m = red[0];
    __syncthreads();

    float lsum = 0.f;
    for (int i = tid; i < NL; i += 256) {
        float e = __expf(sv[i] - m);
        sv[i] = e;
        lsum += e;
    }
    red[tid] = lsum;
    __syncthreads();
    #pragma unroll
    for (int s = 128; s > 0; s >>= 1) {
        if (tid < s) red[tid] += red[tid + s];
        __syncthreads();
    }
    float inv = 1.0f / red[0];
    __syncthreads();

    float* orow = out + (size_t)u * CC;
    for (int c = tid; c < CC; c += 256) {
        int b = offs[c], e = offs[c + 1];
        float s = 0.f;
        for (int j = b; j < e; j++) s += sv[perm[j]];
        orow[c] = s * inv;
    }
}

// ---------------- launch ------------------------------------------------------
extern "C" void kernel_launch(void* const* d_in, const int* in_sizes, int n_in,
                              void* d_out, int out_size) {
    const float* anchor = (const float*)d_in[0];
    const float* pos    = (const float*)d_in[1];
    const float* lb     = (const float*)d_in[2];
    const float* oh     = (const float*)d_in[3];
    const float* lgx    = (const float*)d_in[4];
    float* out = (float*)d_out;

    const size_t nA  = (size_t)NU * DD;
    const size_t nP  = (size_t)NU * DD;
    const size_t nL  = (size_t)2 * NL * DD;
    const size_t nOH = (size_t)2 * NL * CC;
    const size_t nLG = (size_t)2 * NL * CC;
    size_t oA  = 0;
    size_t oP  = oA + nA;
    size_t oL  = oP + nP;
    size_t oOH = oL + nL;
    size_t oLG = oOH + nOH;
    size_t oU1 = oLG + nLG;
    size_t oU2 = oU1 + (size_t)NU * CC;

    // pass-through copies
    copy_f4<<<(int)(nA  / 4 + 255) / 256, 256>>>((const float4*)anchor, (float4*)(out + oA),  (int)(nA  / 4));
    copy_f4<<<(int)(nP  / 4 + 255) / 256, 256>>>((const float4*)pos,    (float4*)(out + oP),  (int)(nP  / 4));
    copy_f4<<<(int)(nL  / 4 + 255) / 256, 256>>>((const float4*)lb,     (float4*)(out + oL),  (int)(nL  / 4));
    copy_f4<<<(int)(nOH / 4 + 255) / 256, 256>>>((const float4*)oh,     (float4*)(out + oOH), (int)(nOH / 4));
    copy_f4<<<(int)(nLG / 4 + 255) / 256, 256>>>((const float4*)lgx,    (float4*)(out + oLG), (int)(nLG / 4));

    // labels + counting sort
    labels_k<<<(2 * NL) / 8, 256>>>(oh);
    zero_counts_k<<<(2 * CC + 255) / 256, 256>>>();
    count_k<<<(2 * NL + 255) / 256, 256>>>();
    offsets_k<<<1, 2>>>();
    scatter_k<<<(2 * NL + 255) / 256, 256>>>();

    // l2 normalize -> bf16
    norm_k<<<NU / 8, 256>>>(anchor, 0, NU);
    norm_k<<<NU / 8, 256>>>(pos,    1, NU);
    norm_k<<<(2 * NL) / 8, 256>>>(lb, 2, 2 * NL);

    // tensor-core GEMM, both halves in one grid
    cudaFuncSetAttribute(gemm_mma_k, cudaFuncAttributeMaxDynamicSharedMemorySize, GEMM_SMEM);
    dim3 gg(NL / BN, NU / BM, 2);
    gemm_mma_k<<<gg, 256, GEMM_SMEM>>>();

    // softmax + aggregation
    softmax_agg_k<<<NU, 256>>>(0, out + oU1);
    softmax_agg_k<<<NU, 256>>>(1, out + oU2);
}

// round 5
// speedup vs baseline: 4.7215x; 1.1983x over previous
#include <cuda_runtime.h>
#include <cuda_bf16.h>
#include <math_constants.h>
#include <cstdint>

// Problem constants
#define NU   8192
#define NL   8192     // per half
#define DD   512
#define CC   1000
#define INV_TAU 10.0f

// ---------------- device scratch ---------------------------------------------
__device__ __nv_bfloat16 g_aqh [NU * DD];
__device__ __nv_bfloat16 g_pqh [NU * DD];
__device__ __nv_bfloat16 g_suph[2 * NL * DD];     // class-sorted order!
__device__ float g_logits[2 * (size_t)NU * NL];
__device__ int   g_labels[2 * NL];
__device__ int   g_counts[2 * CC];
__device__ int   g_offsets[2 * (CC + 1)];
__device__ int   g_cursor[2 * CC];
__device__ int   g_perm[2 * NL];

// ---------------- PTX helpers -------------------------------------------------
__device__ __forceinline__ uint32_t smem_u32(const void* p) {
    uint32_t a;
    asm("{ .reg .u64 t; cvta.to.shared.u64 t, %1; cvt.u32.u64 %0, t; }" : "=r"(a) : "l"(p));
    return a;
}
#define CP_ASYNC16(s, g) asm volatile("cp.async.cg.shared.global [%0], [%1], 16;" :: "r"(s), "l"(g))
#define CP_COMMIT()      asm volatile("cp.async.commit_group;" ::: "memory")
#define CP_WAIT(n)       asm volatile("cp.async.wait_group %0;" :: "n"(n) : "memory")

__device__ __forceinline__ void ldsm_x4(uint32_t* r, uint32_t addr) {
    asm volatile("ldmatrix.sync.aligned.m8n8.x4.shared.b16 {%0,%1,%2,%3}, [%4];"
        : "=r"(r[0]), "=r"(r[1]), "=r"(r[2]), "=r"(r[3]) : "r"(addr));
}
__device__ __forceinline__ void ldsm_x2(uint32_t* r, uint32_t addr) {
    asm volatile("ldmatrix.sync.aligned.m8n8.x2.shared.b16 {%0,%1}, [%2];"
        : "=r"(r[0]), "=r"(r[1]) : "r"(addr));
}
__device__ __forceinline__ void mma_bf16(float* c, const uint32_t* a, const uint32_t* b) {
    asm volatile("mma.sync.aligned.m16n8k16.row.col.f32.bf16.bf16.f32 "
        "{%0,%1,%2,%3},{%4,%5,%6,%7},{%8,%9},{%0,%1,%2,%3};"
        : "+f"(c[0]), "+f"(c[1]), "+f"(c[2]), "+f"(c[3])
        : "r"(a[0]), "r"(a[1]), "r"(a[2]), "r"(a[3]), "r"(b[0]), "r"(b[1]));
}

// ---------------- copies ------------------------------------------------------
__global__ void copy_f4(const float4* __restrict__ src, float4* __restrict__ dst, int n4) {
    int i = blockIdx.x * blockDim.x + threadIdx.x;
    if (i < n4) dst[i] = src[i];
}

// ---------------- labels + counting sort -------------------------------------
__global__ void labels_k(const float* __restrict__ oh) {
    int row  = blockIdx.x * (blockDim.x >> 5) + (threadIdx.x >> 5);
    int lane = threadIdx.x & 31;
    if (row >= 2 * NL) return;
    const float* r = oh + (size_t)row * CC;
    int lab = -1;
    for (int c = lane; c < CC; c += 32)
        if (r[c] > 0.5f) lab = c;
    #pragma unroll
    for (int o = 16; o; o >>= 1) lab = max(lab, __shfl_xor_sync(0xffffffffu, lab, o));
    if (lane == 0) g_labels[row] = lab;
}
__global__ void zero_counts_k() {
    int i = blockIdx.x * blockDim.x + threadIdx.x;
    if (i < 2 * CC) g_counts[i] = 0;
}
__global__ void count_k() {
    int i = blockIdx.x * blockDim.x + threadIdx.x;
    if (i >= 2 * NL) return;
    int half = i / NL;
    atomicAdd(&g_counts[half * CC + g_labels[i]], 1);
}
__global__ void offsets_k() {
    int h = threadIdx.x;
    if (h >= 2) return;
    int off = 0;
    for (int c = 0; c < CC; c++) {
        g_offsets[h * (CC + 1) + c] = off;
        g_cursor[h * CC + c] = off;
        off += g_counts[h * CC + c];
    }
    g_offsets[h * (CC + 1) + CC] = off;
}
__global__ void scatter_k() {
    int i = blockIdx.x * blockDim.x + threadIdx.x;
    if (i >= 2 * NL) return;
    int half = i / NL;
    int s    = i - half * NL;
    int pos  = atomicAdd(&g_cursor[half * CC + g_labels[i]], 1);
    g_perm[half * NL + pos] = s;
}

// ---------------- l2 normalize -> bf16 ---------------------------------------
// anchors/positives: identity order
__global__ void norm_q_k(const float* __restrict__ src, int sel) {
    int row  = blockIdx.x * (blockDim.x >> 5) + (threadIdx.x >> 5);
    int lane = threadIdx.x & 31;
    if (row >= NU) return;
    __nv_bfloat16* dstbase = (sel == 0) ? g_aqh : g_pqh;
    const float* s = src + (size_t)row * DD;
    float v[16];
    float acc = 0.f;
    #pragma unroll
    for (int i = 0; i < 16; i++) { v[i] = s[lane + 32 * i]; acc += v[i] * v[i]; }
    #pragma unroll
    for (int o = 16; o; o >>= 1) acc += __shfl_xor_sync(0xffffffffu, acc, o);
    float inv = 1.0f / fmaxf(sqrtf(acc), 1e-12f);
    __nv_bfloat16* d = dstbase + (size_t)row * DD;
    #pragma unroll
    for (int i = 0; i < 16; i++) d[lane + 32 * i] = __float2bfloat16(v[i] * inv);
}
// supports: write in class-sorted (perm) order
__global__ void norm_sup_k(const float* __restrict__ lb) {
    int row  = blockIdx.x * (blockDim.x >> 5) + (threadIdx.x >> 5);  // dest row 0..2NL
    int lane = threadIdx.x & 31;
    if (row >= 2 * NL) return;
    int half = row / NL;
    int pos  = row - half * NL;
    int srow = half * NL + g_perm[half * NL + pos];
    const float* s = lb + (size_t)srow * DD;
    float v[16];
    float acc = 0.f;
    #pragma unroll
    for (int i = 0; i < 16; i++) { v[i] = s[lane + 32 * i]; acc += v[i] * v[i]; }
    #pragma unroll
    for (int o = 16; o; o >>= 1) acc += __shfl_xor_sync(0xffffffffu, acc, o);
    float inv = 1.0f / fmaxf(sqrtf(acc), 1e-12f);
    __nv_bfloat16* d = g_suph + (size_t)row * DD;
    #pragma unroll
    for (int i = 0; i < 16; i++) d[lane + 32 * i] = __float2bfloat16(v[i] * inv);
}

// ---------------- bf16 mma.sync GEMM: logits = (Q @ K^T) * INV_TAU -----------
// 128x128 tile, BK=32, 8 warps (each 64x32), 4-stage cp.async, 1 sync/iter.
#define BM 128
#define BN 128
#define BKK 32
#define STAGES 4
#define NKIT (DD / BKK)                 // 16
#define SROW 80
#define TILE_BYTES (BM * SROW)          // 10240
#define STAGE_BYTES (2 * TILE_BYTES)    // 20480
#define GEMM_SMEM (STAGES * STAGE_BYTES)  // 81920

__global__ void __launch_bounds__(256) gemm_mma_k() {
    extern __shared__ __align__(16) char smem[];
    const uint32_t sbase = smem_u32(smem);

    const int tid  = threadIdx.x;
    const int wid  = tid >> 5;
    const int lane = tid & 31;
    const int wr   = wid & 1;
    const int wc   = wid >> 1;

    const int z  = blockIdx.z;
    const __nv_bfloat16* A = (z == 0) ? g_aqh : g_pqh;
    const __nv_bfloat16* B = g_suph + (size_t)z * NL * DD;
    const int m0 = blockIdx.y * BM;
    const int n0 = blockIdx.x * BN;
    const __nv_bfloat16* Abase = A + (size_t)m0 * DD;
    const __nv_bfloat16* Bbase = B + (size_t)n0 * DD;

    const int r0 = (tid >> 2), r1 = ((tid + 256) >> 2);
    const int c0 = (tid & 3) * 8;

    float acc[4][4][4];
    #pragma unroll
    for (int mi = 0; mi < 4; mi++)
        #pragma unroll
        for (int ni = 0; ni < 4; ni++)
            #pragma unroll
            for (int q = 0; q < 4; q++) acc[mi][ni][q] = 0.f;

    // prefetch stages 0..STAGES-2
    #pragma unroll
    for (int s = 0; s < STAGES - 1; s++) {
        uint32_t sA = sbase + s * STAGE_BYTES;
        uint32_t sB = sA + TILE_BYTES;
        const __nv_bfloat16* Ak = Abase + s * BKK;
        const __nv_bfloat16* Bk = Bbase + s * BKK;
        CP_ASYNC16(sA + r0 * SROW + (c0 * 2), Ak + (size_t)r0 * DD + c0);
        CP_ASYNC16(sA + r1 * SROW + (c0 * 2), Ak + (size_t)r1 * DD + c0);
        CP_ASYNC16(sB + r0 * SROW + (c0 * 2), Bk + (size_t)r0 * DD + c0);
        CP_ASYNC16(sB + r1 * SROW + (c0 * 2), Bk + (size_t)r1 * DD + c0);
        CP_COMMIT();
    }

    const uint32_t aOff = (uint32_t)(wr * 64 + (lane & 15)) * SROW + (lane >> 4) * 16;
    const uint32_t bOff = (uint32_t)(wc * 32 + (lane & 7)) * SROW + ((lane >> 3) & 1) * 16;

    for (int kc = 0; kc < NKIT; kc++) {
        const int st = kc % STAGES;
        CP_WAIT(STAGES - 2);
        __syncthreads();   // stage st data visible; stage (kc+3)%4 fully consumed

        const int pf = kc + STAGES - 1;
        if (pf < NKIT) {
            const int ps = pf % STAGES;
            uint32_t sA = sbase + ps * STAGE_BYTES;
            uint32_t sB = sA + TILE_BYTES;
            const __nv_bfloat16* Ak = Abase + pf * BKK;
            const __nv_bfloat16* Bk = Bbase + pf * BKK;
            CP_ASYNC16(sA + r0 * SROW + (c0 * 2), Ak + (size_t)r0 * DD + c0);
            CP_ASYNC16(sA + r1 * SROW + (c0 * 2), Ak + (size_t)r1 * DD + c0);
            CP_ASYNC16(sB + r0 * SROW + (c0 * 2), Bk + (size_t)r0 * DD + c0);
            CP_ASYNC16(sB + r1 * SROW + (c0 * 2), Bk + (size_t)r1 * DD + c0);
        }
        CP_COMMIT();

        const uint32_t sA = sbase + st * STAGE_BYTES;
        const uint32_t sB = sA + TILE_BYTES;
        #pragma unroll
        for (int kk = 0; kk < 2; kk++) {
            uint32_t aF[4][4], bF[4][2];
            #pragma unroll
            for (int mi = 0; mi < 4; mi++)
                ldsm_x4(aF[mi], sA + aOff + (uint32_t)mi * 16 * SROW + kk * 32);
            #pragma unroll
            for (int ni = 0; ni < 4; ni++)
                ldsm_x2(bF[ni], sB + bOff + (uint32_t)ni * 8 * SROW + kk * 32);
            #pragma unroll
            for (int mi = 0; mi < 4; mi++)
                #pragma unroll
                for (int ni = 0; ni < 4; ni++)
                    mma_bf16(acc[mi][ni], aF[mi], bF[ni]);
        }
    }

    // epilogue
    float* outz = g_logits + (size_t)z * NU * NL;
    const int erow = m0 + wr * 64 + (lane >> 2);
    const int ecol = n0 + wc * 32 + (lane & 3) * 2;
    #pragma unroll
    for (int mi = 0; mi < 4; mi++) {
        #pragma unroll
        for (int ni = 0; ni < 4; ni++) {
            float2 v0 = make_float2(acc[mi][ni][0] * INV_TAU, acc[mi][ni][1] * INV_TAU);
            float2 v1 = make_float2(acc[mi][ni][2] * INV_TAU, acc[mi][ni][3] * INV_TAU);
            *(float2*)(outz + (size_t)(erow + mi * 16) * NL + ecol + ni * 8) = v0;
            *(float2*)(outz + (size_t)(erow + mi * 16 + 8) * NL + ecol + ni * 8) = v1;
        }
    }
}

// ---------------- fused exp + sum + class aggregation ------------------------
// Logits columns are class-sorted, so class c is the contiguous range
// [offs[c], offs[c+1]). No max pass: |logits| <= 10, exp is fp32-safe.
__global__ void __launch_bounds__(256) softmax_agg_k(float* __restrict__ out) {
    __shared__ float sv[NL];
    __shared__ float red[256];

    int u = blockIdx.x;
    int half = blockIdx.y;
    int tid = threadIdx.x;
    const float* lrow = g_logits + (size_t)half * NU * NL + (size_t)u * NL;
    const int* offs = g_offsets + half * (CC + 1);

    float lsum = 0.f;
    #pragma unroll 4
    for (int i = tid; i < NL; i += 256) {
        float e = __expf(lrow[i]);
        sv[i] = e;
        lsum += e;
    }
    red[tid] = lsum;
    __syncthreads();
    #pragma unroll
    for (int s = 128; s > 0; s >>= 1) {
        if (tid < s) red[tid] += red[tid + s];
        __syncthreads();
    }
    float inv = 1.0f / red[0];

    float* orow = out + (size_t)half * NU * CC + (size_t)u * CC;
    for (int c = tid; c < CC; c += 256) {
        int b = offs[c], e = offs[c + 1];
        float s = 0.f;
        for (int j = b; j < e; j++) s += sv[j];
        orow[c] = s * inv;
    }
}

// ---------------- launch ------------------------------------------------------
extern "C" void kernel_launch(void* const* d_in, const int* in_sizes, int n_in,
                              void* d_out, int out_size) {
    const float* anchor = (const float*)d_in[0];
    const float* pos    = (const float*)d_in[1];
    const float* lb     = (const float*)d_in[2];
    const float* oh     = (const float*)d_in[3];
    const float* lgx    = (const float*)d_in[4];
    float* out = (float*)d_out;

    const size_t nA  = (size_t)NU * DD;
    const size_t nP  = (size_t)NU * DD;
    const size_t nL  = (size_t)2 * NL * DD;
    const size_t nOH = (size_t)2 * NL * CC;
    const size_t nLG = (size_t)2 * NL * CC;
    size_t oA  = 0;
    size_t oP  = oA + nA;
    size_t oL  = oP + nP;
    size_t oOH = oL + nL;
    size_t oLG = oOH + nOH;
    size_t oU1 = oLG + nLG;

    // pass-through copies
    copy_f4<<<(int)(nA  / 4 + 255) / 256, 256>>>((const float4*)anchor, (float4*)(out + oA),  (int)(nA  / 4));
    copy_f4<<<(int)(nP  / 4 + 255) / 256, 256>>>((const float4*)pos,    (float4*)(out + oP),  (int)(nP  / 4));
    copy_f4<<<(int)(nL  / 4 + 255) / 256, 256>>>((const float4*)lb,     (float4*)(out + oL),  (int)(nL  / 4));
    copy_f4<<<(int)(nOH / 4 + 255) / 256, 256>>>((const float4*)oh,     (float4*)(out + oOH), (int)(nOH / 4));
    copy_f4<<<(int)(nLG / 4 + 255) / 256, 256>>>((const float4*)lgx,    (float4*)(out + oLG), (int)(nLG / 4));

    // labels + counting sort
    labels_k<<<(2 * NL) / 8, 256>>>(oh);
    zero_counts_k<<<(2 * CC + 255) / 256, 256>>>();
    count_k<<<(2 * NL + 255) / 256, 256>>>();
    offsets_k<<<1, 2>>>();
    scatter_k<<<(2 * NL + 255) / 256, 256>>>();

    // l2 normalize -> bf16 (supports in class-sorted order)
    norm_q_k<<<NU / 8, 256>>>(anchor, 0);
    norm_q_k<<<NU / 8, 256>>>(pos,    1);
    norm_sup_k<<<(2 * NL) / 8, 256>>>(lb);

    // tensor-core GEMM, both halves
    cudaFuncSetAttribute(gemm_mma_k, cudaFuncAttributeMaxDynamicSharedMemorySize, GEMM_SMEM);
    dim3 gg(NL / BN, NU / BM, 2);
    gemm_mma_k<<<gg, 256, GEMM_SMEM>>>();

    // fused exp + sum + segment aggregation, both halves
    dim3 ga(NU, 2);
    softmax_agg_k<<<ga, 256>>>(out + oU1);
}